// round 16
// baseline (speedup 1.0000x reference)
#include <cuda_runtime.h>
#include <cuda_fp16.h>
#include <mma.h>
#include <math.h>

using namespace nvcuda;

// Problem constants
#define NN 100000
#define FF 512
#define HH 128
#define HH2 256
#define EE 1600000
#define CC 64
#define NFf 100000.0f
#define LN_EPS 1e-5f
#define GW 0.8f

// ---------------- scratch (device globals; allocation-free) ----------------
__device__ __half g_xh[(size_t)NN * FF];
__device__ __half g_ht[(size_t)NN * HH];
__device__ __half g_hg[(size_t)NN * HH];
__device__ __half g_q[(size_t)NN * HH2];
__device__ __half g_k[(size_t)NN * HH2];
__device__ __half g_v[(size_t)NN * HH2];
__device__ __half g_x1[(size_t)NN * HH];
__device__ __half g_agg[(size_t)NN * HH];
__device__ __half g_y[(size_t)NN * HH];
__device__ float g_kvs[2 * HH * HH];
__device__ __half g_kvs2h[HH2 * HH2];   // block-diag half
__device__ float g_red[2];
__device__ float g_ksum[HH2];
// packed fp16 weights:
//   [0, 131072)        FC2: 512 rows x 256 cols = [Wt | Wg]
//   [131072, 229376)   QKV: 128 rows x 768 cols = [Wq | Wk | Wv]
//   [229376, 245760)   CONV: 128 x 128
//   [245760, 253952)   FC: 128 x 64 (+pad)
#define WOFF_FC2 0
#define WOFF_QKV 131072
#define WOFF_CONV 229376
#define WOFF_FC 245760
#define WTOTAL 253952
__device__ __half g_wbuf[WTOTAL + 128];
// CSR machinery
__device__ int g_cnt[NN];
__device__ int g_rowptr[NN + 1];
__device__ int g_cursor[NN];
__device__ int g_csr[EE];
__device__ float g_f[NN];
__device__ int g_bsum[128];

// ---------------- utility ----------------
__global__ void zeros_all(float* red, float* ksum, float* kvs) {
    int i = blockIdx.x * blockDim.x + threadIdx.x;
    int stride = gridDim.x * blockDim.x;
    for (int j = i; j < 2 * HH * HH; j += stride) kvs[j] = 0.0f;
    if (i < HH2) ksum[i] = 0.0f;
    if (i < 2) red[i] = 0.0f;
}
__global__ void zero_int_kernel(int* p, size_t n) {
    size_t i = (size_t)blockIdx.x * blockDim.x + threadIdx.x;
    size_t stride = (size_t)gridDim.x * blockDim.x;
    for (; i < n; i += stride) p[i] = 0;
}

__device__ __forceinline__ float warpAllSum(float v) {
    unsigned m = 0xffffffffu;
    v += __shfl_xor_sync(m, v, 16);
    v += __shfl_xor_sync(m, v, 8);
    v += __shfl_xor_sync(m, v, 4);
    v += __shfl_xor_sync(m, v, 2);
    v += __shfl_xor_sync(m, v, 1);
    return v;
}

__device__ __forceinline__ float4 h4f(const __half* p) {
    uint2 u = *(const uint2*)p;
    __half2 h0 = *(__half2*)&u.x, h1 = *(__half2*)&u.y;
    float2 a = __half22float2(h0), b = __half22float2(h1);
    return make_float4(a.x, a.y, b.x, b.y);
}
__device__ __forceinline__ void f4h(__half* p, float4 v) {
    __half2 a = __floats2half2_rn(v.x, v.y), b = __floats2half2_rn(v.z, v.w);
    uint2 u;
    u.x = *(unsigned*)&a;
    u.y = *(unsigned*)&b;
    *(uint2*)p = u;
}
__device__ __forceinline__ void red_add_v4(float* p, float4 v) {
    asm volatile("red.global.add.v4.f32 [%0], {%1,%2,%3,%4};"
                 :: "l"(p), "f"(v.x), "f"(v.y), "f"(v.z), "f"(v.w) : "memory");
}
__device__ __forceinline__ void cp16h(__half* smem, const __half* gmem, bool pred) {
    unsigned saddr = (unsigned)__cvta_generic_to_shared(smem);
    int sz = pred ? 16 : 0;
    asm volatile("cp.async.cg.shared.global [%0], [%1], 16, %2;"
                 :: "r"(saddr), "l"(gmem), "r"(sz));
}

// x -> half
__global__ void x2h_kernel(const float* __restrict__ x, __half* __restrict__ xh) {
    size_t total4 = (size_t)NN * FF / 4;
    size_t i = (size_t)blockIdx.x * blockDim.x + threadIdx.x;
    size_t stride = (size_t)gridDim.x * blockDim.x;
    for (; i < total4; i += stride) {
        float4 v = ((const float4*)x)[i];
        f4h(xh + i * 4, v);
    }
}

// weights -> packed half layouts
__global__ void round_weights_kernel(const float* __restrict__ wt, const float* __restrict__ wg,
                                     const float* __restrict__ wq, const float* __restrict__ wk,
                                     const float* __restrict__ wv, const float* __restrict__ wc,
                                     const float* __restrict__ wf, __half* __restrict__ dst) {
    int i = blockIdx.x * blockDim.x + threadIdx.x;
    int stride = gridDim.x * blockDim.x;
    for (int j = i; j < WTOTAL + 128; j += stride) {
        float v;
        if (j < WOFF_QKV) {
            int r = j >> 8, c = j & 255;
            v = (c < 128) ? wt[r * 128 + c] : wg[r * 128 + (c - 128)];
        } else if (j < WOFF_CONV) {
            int j2 = j - WOFF_QKV;
            int r = j2 / 768, c = j2 % 768;
            int sel = c >> 8, cc = c & 255;
            v = (sel == 0) ? wq[r * 256 + cc] : (sel == 1) ? wk[r * 256 + cc] : wv[r * 256 + cc];
        } else if (j < WOFF_FC) {
            v = wc[j - WOFF_CONV];
        } else if (j < WTOTAL) {
            v = wf[j - WOFF_FC];
        } else v = 0.0f;
        dst[j] = __float2half_rn(v);
    }
}

// build block-diag half kvs2 from float kvs
__global__ void kvs2h_kernel(const float* __restrict__ kvs, __half* __restrict__ kvs2h) {
    int i = blockIdx.x * blockDim.x + threadIdx.x;
    int stride = gridDim.x * blockDim.x;
    for (int j = i; j < HH2 * HH2; j += stride) {
        int r = j >> 8, c = j & 255;
        int h = r >> 7;
        float v = ((c >> 7) == h) ? kvs[h * HH * HH + (r & 127) * HH + (c & 127)] : 0.0f;
        kvs2h[j] = __float2half_rn(v);
    }
}

// ---------------- fragment typedefs ----------------
typedef wmma::fragment<wmma::accumulator, 16, 16, 16, float> FragAcc;
typedef wmma::fragment<wmma::matrix_a, 16, 16, 16, __half, wmma::row_major> HFragA;
typedef wmma::fragment<wmma::matrix_a, 16, 16, 16, __half, wmma::col_major> HFragAT;
typedef wmma::fragment<wmma::matrix_b, 16, 16, 16, __half, wmma::row_major> HFragB;

#define BM 64
#define HA_LD 40
#define HA_STAGE (BM * HA_LD)   // 2560 halfs
#define NSTG 3

// ============ FP16 tensor GEMM core: BM=64, BN templated, BK=32, 3-stage ============
template <int BNT>
__device__ __forceinline__ void gemm_core_h(
    const __half* __restrict__ A, int lda, int M, int bm,
    const __half* __restrict__ B, int ldb, int bn,
    int K, float* smf) {
    __half* sm = (__half*)smf;
    constexpr int BS_LD = BNT + 8;
    constexpr int B_STAGE = 32 * BS_LD;
    constexpr int STG = HA_STAGE + B_STAGE;
    constexpr int WCW = (BNT == 128) ? 32 : 64;
    constexpr int NFR = WCW / 16;

    const int tid = threadIdx.x;
    const int wid = tid >> 5;
    const int wr = wid >> 2;  // 0..1
    const int wc = wid & 3;   // 0..3

    FragAcc acc[2][NFR];
#pragma unroll
    for (int i = 0; i < 2; i++)
#pragma unroll
        for (int j = 0; j < NFR; j++) wmma::fill_fragment(acc[i][j], 0.0f);

    const int T = K >> 5;

    auto load_stage = [&](int t, int s) {
        const int k0 = t << 5;
        __half* sA = sm + s * STG;
        __half* sB = sm + s * STG + HA_STAGE;
        {
            int r = tid >> 2, c8 = (tid & 3) * 8;
            bool ok = (bm + r) < M;
            cp16h(sA + r * HA_LD + c8, A + (size_t)(ok ? bm + r : 0) * lda + k0 + c8, ok);
        }
#pragma unroll
        for (int j = 0; j < BNT / 64; j++) {
            int idx = tid + j * 256;
            int r = idx / (BNT / 8), c8 = (idx % (BNT / 8)) * 8;
            cp16h(sB + r * BS_LD + c8, B + (size_t)(k0 + r) * ldb + bn + c8, true);
        }
        asm volatile("cp.async.commit_group;");
    };

#pragma unroll
    for (int t = 0; t < NSTG - 1; t++) {
        if (t < T) load_stage(t, t);
        else asm volatile("cp.async.commit_group;");
    }

    int s = 0;
    for (int t = 0; t < T; t++) {
        asm volatile("cp.async.wait_group %0;" :: "n"(NSTG - 2));
        __syncthreads();
        int tn = t + NSTG - 1;
        int sn = s + NSTG - 1;
        if (sn >= NSTG) sn -= NSTG;
        if (tn < T) load_stage(tn, sn);
        else asm volatile("cp.async.commit_group;");

        const __half* sA = sm + s * STG;
        const __half* sB = sm + s * STG + HA_STAGE;
#pragma unroll
        for (int ks = 0; ks < 2; ks++) {
            HFragA af[2];
#pragma unroll
            for (int mi = 0; mi < 2; mi++)
                wmma::load_matrix_sync(af[mi], sA + (wr * 32 + mi * 16) * HA_LD + ks * 16, HA_LD);
#pragma unroll
            for (int ni = 0; ni < NFR; ni++) {
                HFragB bf;
                wmma::load_matrix_sync(bf, sB + (ks * 16) * BS_LD + wc * WCW + ni * 16, BS_LD);
                wmma::mma_sync(acc[0][ni], af[0], bf, acc[0][ni]);
                wmma::mma_sync(acc[1][ni], af[1], bf, acc[1][ni]);
            }
        }
        if (++s == NSTG) s = 0;
    }
    __syncthreads();

#pragma unroll
    for (int mi = 0; mi < 2; mi++)
#pragma unroll
        for (int ni = 0; ni < NFR; ni++)
            wmma::store_matrix_sync(smf + (wr * 32 + mi * 16) * BNT + wc * WCW + ni * 16,
                                    acc[mi][ni], BNT, wmma::mem_row_major);
    __syncthreads();
}

#define SM128 41472   // max(3 stages * 6912 halfs * 2B, 64*128*4B staging)
#define SM256 66048   // max(3 stages * 11008 halfs * 2B, 64*256*4B staging)

// ---- combined FC GEMM: C[:,0:128]=x@Wt -> LN -> ht ; C[:,128:256]=x@Wg -> BN -> hg
__global__ void __launch_bounds__(256, 3) gemm_fc_comb(
    const __half* __restrict__ xh, const __half* __restrict__ wbuf,
    const float* __restrict__ bt, const float* __restrict__ ln_g, const float* __restrict__ ln_b,
    const float* __restrict__ bg, const float* __restrict__ bn_g, const float* __restrict__ bn_b,
    __half* __restrict__ ht, __half* __restrict__ hg) {
    extern __shared__ float sm[];
    const int bm = blockIdx.x * BM;
    gemm_core_h<256>(xh, FF, NN, bm, wbuf + WOFF_FC2, HH2, 0, FF, sm);

    const int tid = threadIdx.x;
    const int wid = tid >> 5;
    const int lane = tid & 31;

    // LN part (cols 0..127)
    {
        float4 bb = *(const float4*)(bt + lane * 4);
        float4 gg = *(const float4*)(ln_g + lane * 4);
        float4 be = *(const float4*)(ln_b + lane * 4);
#pragma unroll
        for (int i = 0; i < 8; i++) {
            int r = wid * 8 + i;
            int m = bm + r;
            float4 v = *(float4*)(sm + r * 256 + lane * 4);
            v.x += bb.x; v.y += bb.y; v.z += bb.z; v.w += bb.w;
            float mu = warpAllSum(v.x + v.y + v.z + v.w) * (1.0f / 128.0f);
            float4 d = make_float4(v.x - mu, v.y - mu, v.z - mu, v.w - mu);
            float var = warpAllSum(d.x * d.x + d.y * d.y + d.z * d.z + d.w * d.w) * (1.0f / 128.0f);
            float rs = rsqrtf(var + LN_EPS);
            float4 o;
            o.x = fmaxf(d.x * rs * gg.x + be.x, 0.f);
            o.y = fmaxf(d.y * rs * gg.y + be.y, 0.f);
            o.z = fmaxf(d.z * rs * gg.z + be.z, 0.f);
            o.w = fmaxf(d.w * rs * gg.w + be.w, 0.f);
            if (m < NN) f4h(ht + (size_t)m * HH + lane * 4, o);
        }
    }
    // BN part (cols 128..255)
    {
        int c4 = lane * 4;
        int r0 = wid;
        const float sbn = rsqrtf(1.0f + LN_EPS);
        float4 bb = *(const float4*)(bg + c4);
        float4 gg = *(const float4*)(bn_g + c4);
        float4 be = *(const float4*)(bn_b + c4);
        gg.x *= sbn; gg.y *= sbn; gg.z *= sbn; gg.w *= sbn;
#pragma unroll
        for (int j = 0; j < 8; j++) {
            int r = r0 + j * 8;
            int m = bm + r;
            if (m < NN) {
                float4 v = *(float4*)(sm + r * 256 + 128 + c4);
                float4 o;
                o.x = fmaxf((v.x + bb.x) * gg.x + be.x, 0.f);
                o.y = fmaxf((v.y + bb.y) * gg.y + be.y, 0.f);
                o.z = fmaxf((v.z + bb.z) * gg.z + be.z, 0.f);
                o.w = fmaxf((v.w + bb.w) * gg.w + be.w, 0.f);
                f4h(hg + (size_t)m * HH + c4, o);
            }
        }
    }
}

// ---- QKV: grid.x = 3 (sel -> q/k/v, full 256-wide result) + norm/ksum reductions ----
__global__ void __launch_bounds__(256, 3) gemm_qkv(
    const __half* __restrict__ ht, const __half* __restrict__ wbuf,
    const float* __restrict__ bq, const float* __restrict__ bk, const float* __restrict__ bv,
    __half* __restrict__ q, __half* __restrict__ k, __half* __restrict__ v,
    float* __restrict__ red, float* __restrict__ ksum) {
    extern __shared__ float sm[];
    __shared__ float rsh[1];
    __shared__ float ks_s[HH2];
    const int sel = blockIdx.x;
    const int bm = blockIdx.y * BM;
    const float* bias = (sel == 0 ? bq : (sel == 1 ? bk : bv));
    __half* C = (sel == 0 ? q : (sel == 1 ? k : v));
    gemm_core_h<256>(ht, HH, NN, bm, wbuf + WOFF_QKV, 768, sel * 256, HH, sm);

    const int tid = threadIdx.x;
    int c4 = (tid & 63) * 4;        // 0..252
    int r0 = tid >> 6;              // 0..3
    float4 bb = *(const float4*)(bias + c4);

    if (sel == 1) ks_s[tid] = 0.0f;
    if (tid == 0) rsh[0] = 0.0f;
    __syncthreads();

    float sq = 0.0f;
    float4 cs = make_float4(0.f, 0.f, 0.f, 0.f);
#pragma unroll
    for (int j = 0; j < 16; j++) {
        int r = r0 + j * 4;
        int m = bm + r;
        if (m < NN) {
            float4 o = *(float4*)(sm + r * 256 + c4);
            o.x += bb.x; o.y += bb.y; o.z += bb.z; o.w += bb.w;
            if (sel < 2) sq += o.x * o.x + o.y * o.y + o.z * o.z + o.w * o.w;
            if (sel == 1) { cs.x += o.x; cs.y += o.y; cs.z += o.z; cs.w += o.w; }
            f4h(C + (size_t)m * HH2 + c4, o);
        }
    }

    if (sel < 2) {
        float ws = warpAllSum(sq);
        if ((tid & 31) == 0) atomicAdd(&rsh[0], ws);
        __syncthreads();
        if (tid == 0) atomicAdd(&red[sel], rsh[0]);
    }
    if (sel == 1) {
        atomicAdd(&ks_s[c4 + 0], cs.x);
        atomicAdd(&ks_s[c4 + 1], cs.y);
        atomicAdd(&ks_s[c4 + 2], cs.z);
        atomicAdd(&ks_s[c4 + 3], cs.w);
        __syncthreads();
        atomicAdd(&ksum[tid], ks_s[tid]);
    }
}

// ---- num over block-diag kvs2h + fused finalize -> x1 (half) ----
__global__ void __launch_bounds__(256, 3) gemm_num_fin(
    const __half* __restrict__ q, const __half* __restrict__ kvs2h,
    const __half* __restrict__ v, const __half* __restrict__ ht,
    const float* __restrict__ ksum, const float* __restrict__ red,
    const float* __restrict__ ln_g, const float* __restrict__ ln_b,
    __half* __restrict__ x1) {
    extern __shared__ float sm[];
    const int bm = blockIdx.x * BM;
    gemm_core_h<256>(q, HH2, NN, bm, kvs2h, HH2, 0, HH2, sm);

    const int tid = threadIdx.x;
    const int wid = tid >> 5;
    const int lane = tid & 31;
    const float inv = rsqrtf(red[0]) * rsqrtf(red[1]);

    float4 ka = *(const float4*)(ksum + lane * 8);
    float4 kb = *(const float4*)(ksum + lane * 8 + 4);
    float4 gg = *(const float4*)(ln_g + lane * 4);
    float4 be = *(const float4*)(ln_b + lane * 4);

#pragma unroll
    for (int i = 0; i < 8; i++) {
        int r = wid * 8 + i;
        int m = bm + r;
        if (m >= NN) continue;  // uniform per warp
        const __half* qrow = q + (size_t)m * HH2 + lane * 8;
        float4 qa = h4f(qrow);
        float4 qb = h4f(qrow + 4);
        float part = qa.x * ka.x + qa.y * ka.y + qa.z * ka.z + qa.w * ka.w
                   + qb.x * kb.x + qb.y * kb.y + qb.z * kb.z + qb.w * kb.w;
        float s0 = warpAllSum(lane < 16 ? part : 0.0f);
        float s1 = warpAllSum(lane >= 16 ? part : 0.0f);
        float nrm0 = inv * s0 + NFf;
        float nrm1 = inv * s1 + NFf;

        float4 n0 = *(float4*)(sm + r * 256 + lane * 4);
        float4 n1 = *(float4*)(sm + r * 256 + 128 + lane * 4);
        float4 v0 = h4f(v + (size_t)m * HH2 + lane * 4);
        float4 v1 = h4f(v + (size_t)m * HH2 + 128 + lane * 4);
        float4 hv = h4f(ht + (size_t)m * HH + lane * 4);

        float4 xv;
        xv.x = 0.5f * (0.5f * ((inv * n0.x + NFf * v0.x) / nrm0 + (inv * n1.x + NFf * v1.x) / nrm1) + hv.x);
        xv.y = 0.5f * (0.5f * ((inv * n0.y + NFf * v0.y) / nrm0 + (inv * n1.y + NFf * v1.y) / nrm1) + hv.y);
        xv.z = 0.5f * (0.5f * ((inv * n0.z + NFf * v0.z) / nrm0 + (inv * n1.z + NFf * v1.z) / nrm1) + hv.z);
        xv.w = 0.5f * (0.5f * ((inv * n0.w + NFf * v0.w) / nrm0 + (inv * n1.w + NFf * v1.w) / nrm1) + hv.w);

        float mu = warpAllSum(xv.x + xv.y + xv.z + xv.w) * (1.0f / 128.0f);
        float4 d = make_float4(xv.x - mu, xv.y - mu, xv.z - mu, xv.w - mu);
        float var = warpAllSum(d.x * d.x + d.y * d.y + d.z * d.z + d.w * d.w) * (1.0f / 128.0f);
        float rs = rsqrtf(var + LN_EPS);
        float4 o;
        o.x = fmaxf(d.x * rs * gg.x + be.x, 0.f);
        o.y = fmaxf(d.y * rs * gg.y + be.y, 0.f);
        o.z = fmaxf(d.z * rs * gg.z + be.z, 0.f);
        o.w = fmaxf(d.w * rs * gg.w + be.w, 0.f);
        f4h(x1 + (size_t)m * HH + lane * 4, o);
    }
}

// ---- conv GEMM + BN/relu/residual/mix -> y (half) ----
__global__ void __launch_bounds__(256, 3) gemm_conv_cmb(
    const __half* __restrict__ agg, const __half* __restrict__ wbuf,
    const float* __restrict__ bias, const float* __restrict__ bn_g, const float* __restrict__ bn_b,
    const __half* __restrict__ hg, const __half* __restrict__ x1,
    __half* __restrict__ y) {
    extern __shared__ float sm[];
    const int bm = blockIdx.x * BM;
    gemm_core_h<128>(agg, HH, NN, bm, wbuf + WOFF_CONV, HH, 0, HH, sm);

    const int tid = threadIdx.x;
    int c4 = (tid & 31) * 4;
    int r0 = tid >> 5;
    const float sbn = rsqrtf(1.0f + LN_EPS);
    float4 bb = *(const float4*)(bias + c4);
    float4 gg = *(const float4*)(bn_g + c4);
    float4 be = *(const float4*)(bn_b + c4);
    gg.x *= sbn; gg.y *= sbn; gg.z *= sbn; gg.w *= sbn;
#pragma unroll
    for (int j = 0; j < 8; j++) {
        int r = r0 + j * 8;
        int m = bm + r;
        if (m < NN) {
            float4 v = *(float4*)(sm + r * 128 + c4);
            v.x = fmaxf((v.x + bb.x) * gg.x + be.x, 0.f);
            v.y = fmaxf((v.y + bb.y) * gg.y + be.y, 0.f);
            v.z = fmaxf((v.z + bb.z) * gg.z + be.z, 0.f);
            v.w = fmaxf((v.w + bb.w) * gg.w + be.w, 0.f);
            float4 h = h4f(hg + (size_t)m * HH + c4);
            float4 xv = h4f(x1 + (size_t)m * HH + c4);
            float4 o;
            o.x = GW * (v.x + h.x) + (1.0f - GW) * xv.x;
            o.y = GW * (v.y + h.y) + (1.0f - GW) * xv.y;
            o.z = GW * (v.z + h.z) + (1.0f - GW) * xv.z;
            o.w = GW * (v.w + h.w) + (1.0f - GW) * xv.w;
            f4h(y + (size_t)m * HH + c4, o);
        }
    }
}

// ---- final head GEMM: out = y @ fc_w + fc_b (fp32 out) ----
__global__ void __launch_bounds__(256, 3) gemm_out(
    const __half* __restrict__ y, const __half* __restrict__ wbuf,
    const float* __restrict__ bias, float* __restrict__ out) {
    extern __shared__ float sm[];
    const int bm = blockIdx.x * BM;
    gemm_core_h<128>(y, HH, NN, bm, wbuf + WOFF_FC, CC, 0, HH, sm);

    const int tid = threadIdx.x;
    int c4 = (tid & 31) * 4;
    int r0 = tid >> 5;
    if (c4 < CC) {
        float4 bb = *(const float4*)(bias + c4);
#pragma unroll
        for (int j = 0; j < 8; j++) {
            int r = r0 + j * 8;
            int m = bm + r;
            if (m < NN) {
                float4 o = *(float4*)(sm + r * 128 + c4);
                o.x += bb.x; o.y += bb.y; o.z += bb.z; o.w += bb.w;
                *(float4*)(out + (size_t)m * CC + c4) = o;
            }
        }
    }
}

// ============ FP16 split-K kvs -> float kvs (atomics) ============
#define KVS_SMEM 65536
#define KS_LD 136

__global__ void __launch_bounds__(256) kvs_h_kernel(
    const __half* __restrict__ Km, const __half* __restrict__ Vm,
    float* __restrict__ kvs, int KC) {
    extern __shared__ float smf[];
    __half* Ks = (__half*)smf;                 // [32][136]
    __half* Vs = (__half*)smf + 32 * KS_LD;    // [32][136]

    const int tid = threadIdx.x;
    const int wid = tid >> 5;
    const int wr = wid >> 1;  // 0..3
    const int wc = wid & 1;   // 0..1
    const int head = blockIdx.y;
    const __half* Kp = Km + head * HH;
    const __half* Vp = Vm + head * HH;
    float* Cp = kvs + head * HH * HH;
    const int kb = blockIdx.x * KC;
    const int ke = min(kb + KC, NN);

    FragAcc acc[2][4];
#pragma unroll
    for (int i = 0; i < 2; i++)
#pragma unroll
        for (int j = 0; j < 4; j++) wmma::fill_fragment(acc[i][j], 0.0f);

    for (int t = kb; t < ke; t += 32) {
#pragma unroll
        for (int j = 0; j < 2; j++) {
            int idx = tid + j * 256;
            int r = idx >> 4, c8 = (idx & 15) * 8;
            int kr = t + r;
            bool ok = kr < ke;
            cp16h(Ks + r * KS_LD + c8, Kp + (size_t)(ok ? kr : 0) * HH2 + c8, ok);
            cp16h(Vs + r * KS_LD + c8, Vp + (size_t)(ok ? kr : 0) * HH2 + c8, ok);
        }
        asm volatile("cp.async.commit_group;");
        asm volatile("cp.async.wait_group 0;");
        __syncthreads();
#pragma unroll
        for (int ks = 0; ks < 2; ks++) {
            HFragAT af[2];
            wmma::load_matrix_sync(af[0], Ks + (ks * 16) * KS_LD + wr * 32, KS_LD);
            wmma::load_matrix_sync(af[1], Ks + (ks * 16) * KS_LD + wr * 32 + 16, KS_LD);
#pragma unroll
            for (int ni = 0; ni < 4; ni++) {
                HFragB bf;
                wmma::load_matrix_sync(bf, Vs + (ks * 16) * KS_LD + wc * 64 + ni * 16, KS_LD);
                wmma::mma_sync(acc[0][ni], af[0], bf, acc[0][ni]);
                wmma::mma_sync(acc[1][ni], af[1], bf, acc[1][ni]);
            }
        }
        __syncthreads();
    }

    float* stg = smf;
#pragma unroll
    for (int mi = 0; mi < 2; mi++)
#pragma unroll
        for (int ni = 0; ni < 4; ni++)
            wmma::store_matrix_sync(stg + (wr * 32 + mi * 16) * 128 + wc * 64 + ni * 16,
                                    acc[mi][ni], 128, wmma::mem_row_major);
    __syncthreads();

    int oc = (tid & 31) * 4;
    int orr = tid >> 5;
#pragma unroll
    for (int j = 0; j < 16; j++) {
        int r = orr + j * 8;
        float4 v = *(float4*)(stg + r * 128 + oc);
        red_add_v4(Cp + r * 128 + oc, v);
    }
}

// ---------------- CSR build + gather ----------------
__global__ void deg_int_kernel(const int* __restrict__ ei, int* __restrict__ cnt) {
    int i = blockIdx.x * blockDim.x + threadIdx.x;
    int stride = gridDim.x * blockDim.x;
    for (int e = i; e < EE; e += stride) atomicAdd(&cnt[ei[EE + e]], 1);
}

__global__ void f_kernel(const int* __restrict__ cnt, float* __restrict__ f) {
    int i = blockIdx.x * blockDim.x + threadIdx.x;
    int stride = gridDim.x * blockDim.x;
    for (int n = i; n < NN; n += stride)
        f[n] = (cnt[n] > 0) ? rsqrtf((float)cnt[n]) : 0.0f;
}

#define SCAN_NB 98
__global__ void scan_partial(const int* __restrict__ cnt, int* __restrict__ bsum) {
    __shared__ int sh[32];
    int tid = threadIdx.x;
    int i = blockIdx.x * 1024 + tid;
    int v = (i < NN) ? cnt[i] : 0;
    unsigned m = 0xffffffffu;
    int s = v;
    s += __shfl_down_sync(m, s, 16);
    s += __shfl_down_sync(m, s, 8);
    s += __shfl_down_sync(m, s, 4);
    s += __shfl_down_sync(m, s, 2);
    s += __shfl_down_sync(m, s, 1);
    if ((tid & 31) == 0) sh[tid >> 5] = s;
    __syncthreads();
    if (tid < 32) {
        int t = sh[tid];
        t += __shfl_down_sync(m, t, 16);
        t += __shfl_down_sync(m, t, 8);
        t += __shfl_down_sync(m, t, 4);
        t += __shfl_down_sync(m, t, 2);
        t += __shfl_down_sync(m, t, 1);
        if (tid == 0) bsum[blockIdx.x] = t;
    }
}

__global__ void scan_bsum(int* __restrict__ bsum) {
    __shared__ int sh[128];
    int tid = threadIdx.x;
    int v = (tid < SCAN_NB) ? bsum[tid] : 0;
    sh[tid] = v;
    __syncthreads();
    for (int off = 1; off < 128; off <<= 1) {
        int t = (tid >= off) ? sh[tid - off] : 0;
        __syncthreads();
        sh[tid] += t;
        __syncthreads();
    }
    if (tid < SCAN_NB) bsum[tid] = sh[tid] - v;
}

__global__ void scan_final(const int* __restrict__ cnt, const int* __restrict__ bsum,
                           int* __restrict__ rowptr, int* __restrict__ cursor) {
    __shared__ int sh[1024];
    int tid = threadIdx.x;
    int i = blockIdx.x * 1024 + tid;
    int v = (i < NN) ? cnt[i] : 0;
    sh[tid] = v;
    __syncthreads();
    for (int off = 1; off < 1024; off <<= 1) {
        int t = (tid >= off) ? sh[tid - off] : 0;
        __syncthreads();
        sh[tid] += t;
        __syncthreads();
    }
    int ex = sh[tid] - v + bsum[blockIdx.x];
    if (i < NN) {
        rowptr[i] = ex;
        cursor[i] = ex;
    }
    if (i == NN - 1) rowptr[NN] = EE;
}

__global__ void fill_csr(const int* __restrict__ ei, int* __restrict__ cursor,
                         int* __restrict__ csr) {
    int i = blockIdx.x * blockDim.x + threadIdx.x;
    int stride = gridDim.x * blockDim.x;
    for (int e = i; e < EE; e += stride) {
        int c = ei[EE + e];
        int pos = atomicAdd(&cursor[c], 1);
        csr[pos] = ei[e];
    }
}

// one warp per node; lane owns 4 channels; unroll-4 for MLP
__global__ void gather_kernel(const int* __restrict__ rowptr, const int* __restrict__ csr,
                              const float* __restrict__ f, const __half* __restrict__ hg,
                              __half* __restrict__ agg) {
    int lane = threadIdx.x & 31;
    int w = (blockIdx.x * blockDim.x + threadIdx.x) >> 5;
    if (w >= NN) return;
    int n = w;
    int s = rowptr[n], e = rowptr[n + 1];
    float4 a0 = make_float4(0.f, 0.f, 0.f, 0.f);
    float4 a1 = make_float4(0.f, 0.f, 0.f, 0.f);
    int j = s;
    for (; j + 4 <= e; j += 4) {
        int r0 = csr[j], r1 = csr[j + 1], r2 = csr[j + 2], r3 = csr[j + 3];
        float f0 = f[r0], f1 = f[r1], f2 = f[r2], f3 = f[r3];
        float4 h0 = h4f(hg + (size_t)r0 * HH + lane * 4);
        float4 h1 = h4f(hg + (size_t)r1 * HH + lane * 4);
        float4 h2 = h4f(hg + (size_t)r2 * HH + lane * 4);
        float4 h3 = h4f(hg + (size_t)r3 * HH + lane * 4);
        a0.x += f0 * h0.x + f2 * h2.x; a0.y += f0 * h0.y + f2 * h2.y;
        a0.z += f0 * h0.z + f2 * h2.z; a0.w += f0 * h0.w + f2 * h2.w;
        a1.x += f1 * h1.x + f3 * h3.x; a1.y += f1 * h1.y + f3 * h3.y;
        a1.z += f1 * h1.z + f3 * h3.z; a1.w += f1 * h1.w + f3 * h3.w;
    }
    for (; j < e; j++) {
        int r = csr[j];
        float fr = f[r];
        float4 h = h4f(hg + (size_t)r * HH + lane * 4);
        a0.x += fr * h.x; a0.y += fr * h.y; a0.z += fr * h.z; a0.w += fr * h.w;
    }
    float fc = f[n];
    float4 acc = make_float4(fc * (a0.x + a1.x), fc * (a0.y + a1.y),
                             fc * (a0.z + a1.z), fc * (a0.w + a1.w));
    f4h(agg + (size_t)n * HH + lane * 4, acc);
}

// ---------------- host launcher ----------------
extern "C" void kernel_launch(void* const* d_in, const int* in_sizes, int n_in,
                              void* d_out, int out_size) {
    const float* x = (const float*)d_in[0];
    const int* ei = (const int*)d_in[1];
    const float* t_fc_w = (const float*)d_in[2];
    const float* t_fc_b = (const float*)d_in[3];
    const float* t_ln0_g = (const float*)d_in[4];
    const float* t_ln0_b = (const float*)d_in[5];
    const float* t_wq_w = (const float*)d_in[6];
    const float* t_wq_b = (const float*)d_in[7];
    const float* t_wk_w = (const float*)d_in[8];
    const float* t_wk_b = (const float*)d_in[9];
    const float* t_wv_w = (const float*)d_in[10];
    const float* t_wv_b = (const float*)d_in[11];
    const float* t_ln1_g = (const float*)d_in[12];
    const float* t_ln1_b = (const float*)d_in[13];
    const float* g_fc_w = (const float*)d_in[14];
    const float* g_fc_b = (const float*)d_in[15];
    const float* g_bn0_g = (const float*)d_in[16];
    const float* g_bn0_b = (const float*)d_in[17];
    const float* g_conv_w = (const float*)d_in[18];
    const float* g_conv_b = (const float*)d_in[19];
    const float* g_bn1_g = (const float*)d_in[20];
    const float* g_bn1_b = (const float*)d_in[21];
    const float* fc_w = (const float*)d_in[22];
    const float* fc_b = (const float*)d_in[23];
    float* out = (float*)d_out;

    cudaFuncSetAttribute(gemm_fc_comb, cudaFuncAttributeMaxDynamicSharedMemorySize, SM256);
    cudaFuncSetAttribute(gemm_qkv, cudaFuncAttributeMaxDynamicSharedMemorySize, SM256);
    cudaFuncSetAttribute(gemm_num_fin, cudaFuncAttributeMaxDynamicSharedMemorySize, SM256);
    cudaFuncSetAttribute(gemm_conv_cmb, cudaFuncAttributeMaxDynamicSharedMemorySize, SM128);
    cudaFuncSetAttribute(gemm_out, cudaFuncAttributeMaxDynamicSharedMemorySize, SM128);
    cudaFuncSetAttribute(kvs_h_kernel, cudaFuncAttributeMaxDynamicSharedMemorySize, KVS_SMEM);

    __half *p_xh, *p_ht, *p_hg, *p_q, *p_k, *p_v, *p_x1, *p_agg, *p_y, *p_kvs2h, *p_wbuf;
    float *p_kvs, *p_red, *p_ksum, *p_f;
    int *p_cnt, *p_rowptr, *p_cursor, *p_csr, *p_bsum;
    cudaGetSymbolAddress((void**)&p_xh, g_xh);
    cudaGetSymbolAddress((void**)&p_ht, g_ht);
    cudaGetSymbolAddress((void**)&p_hg, g_hg);
    cudaGetSymbolAddress((void**)&p_q, g_q);
    cudaGetSymbolAddress((void**)&p_k, g_k);
    cudaGetSymbolAddress((void**)&p_v, g_v);
    cudaGetSymbolAddress((void**)&p_x1, g_x1);
    cudaGetSymbolAddress((void**)&p_agg, g_agg);
    cudaGetSymbolAddress((void**)&p_y, g_y);
    cudaGetSymbolAddress((void**)&p_kvs2h, g_kvs2h);
    cudaGetSymbolAddress((void**)&p_wbuf, g_wbuf);
    cudaGetSymbolAddress((void**)&p_kvs, g_kvs);
    cudaGetSymbolAddress((void**)&p_red, g_red);
    cudaGetSymbolAddress((void**)&p_ksum, g_ksum);
    cudaGetSymbolAddress((void**)&p_f, g_f);
    cudaGetSymbolAddress((void**)&p_cnt, g_cnt);
    cudaGetSymbolAddress((void**)&p_rowptr, g_rowptr);
    cudaGetSymbolAddress((void**)&p_cursor, g_cursor);
    cudaGetSymbolAddress((void**)&p_csr, g_csr);
    cudaGetSymbolAddress((void**)&p_bsum, g_bsum);

    const int GY = (NN + BM - 1) / BM;  // 1563

    zeros_all<<<64, 256>>>(p_red, p_ksum, p_kvs);
    x2h_kernel<<<2048, 256>>>(x, p_xh);
    round_weights_kernel<<<248, 256>>>(t_fc_w, g_fc_w, t_wq_w, t_wk_w, t_wv_w,
                                       g_conv_w, fc_w, p_wbuf);

    // ---- combined FC (x read once; LN->ht, BN->hg) ----
    gemm_fc_comb<<<GY, 256, SM256>>>(
        p_xh, p_wbuf, t_fc_b, t_ln0_g, t_ln0_b, g_fc_b, g_bn0_g, g_bn0_b, p_ht, p_hg);

    // ---- QKV (BN=256, grid.x=3, + norms + ksum) ----
    gemm_qkv<<<dim3(3, GY), 256, SM256>>>(
        p_ht, p_wbuf, t_wq_b, t_wk_b, t_wv_b, p_q, p_k, p_v, p_red, p_ksum);

    // ---- kvs (fp16 MMA, fp32 atomic accumulate) ----
    {
        const int KC = 704;
        const int SPLITS = (NN + KC - 1) / KC;
        dim3 grid(SPLITS, 2);
        kvs_h_kernel<<<grid, 256, KVS_SMEM>>>(p_k, p_v, p_kvs, KC);
    }
    kvs2h_kernel<<<64, 256>>>(p_kvs, p_kvs2h);

    // ---- num GEMM + fused finalize -> x1 ----
    gemm_num_fin<<<GY, 256, SM256>>>(
        p_q, p_kvs2h, p_v, p_ht, p_ksum, p_red, t_ln1_g, t_ln1_b, p_x1);

    // ---- Graph branch (CSR + gather) ----
    zero_int_kernel<<<128, 256>>>(p_cnt, NN);
    deg_int_kernel<<<2048, 256>>>(ei, p_cnt);
    f_kernel<<<128, 256>>>(p_cnt, p_f);
    scan_partial<<<SCAN_NB, 1024>>>(p_cnt, p_bsum);
    scan_bsum<<<1, 128>>>(p_bsum);
    scan_final<<<SCAN_NB, 1024>>>(p_cnt, p_bsum, p_rowptr, p_cursor);
    fill_csr<<<2048, 256>>>(ei, p_cursor, p_csr);
    gather_kernel<<<(NN * 32 + 255) / 256, 256>>>(p_rowptr, p_csr, p_f, p_hg, p_agg);

    // ---- combine + head ----
    gemm_conv_cmb<<<GY, 256, SM128>>>(
        p_agg, p_wbuf, g_conv_b, g_bn1_g, g_bn1_b, p_hg, p_x1, p_y);

    gemm_out<<<GY, 256, SM128>>>(p_y, p_wbuf, fc_b, out);
}

// round 17
// speedup vs baseline: 1.2904x; 1.2904x over previous
#include <cuda_runtime.h>
#include <cuda_fp16.h>
#include <mma.h>
#include <math.h>

using namespace nvcuda;

// Problem constants
#define NN 100000
#define FF 512
#define HH 128
#define HH2 256
#define EE 1600000
#define CC 64
#define NFf 100000.0f
#define LN_EPS 1e-5f
#define GW 0.8f

// ---------------- scratch (device globals; allocation-free) ----------------
__device__ __half g_xh[(size_t)NN * FF];
__device__ __half g_ht[(size_t)NN * HH];
__device__ __half g_hg[(size_t)NN * HH];
__device__ __half g_q[(size_t)NN * HH2];
__device__ __half g_k[(size_t)NN * HH2];
__device__ __half g_v[(size_t)NN * HH2];
__device__ __half g_x1[(size_t)NN * HH];
__device__ __half g_agg[(size_t)NN * HH];
__device__ __half g_y[(size_t)NN * HH];
__device__ float g_kvs[2 * HH * HH];
__device__ __half g_kvs2h[HH2 * HH2];   // block-diag half
__device__ float g_red[2];
__device__ float g_ksum[HH2];
// packed fp16 weights:
//   [0, 131072)        FC2: 512 rows x 256 cols = [Wt | Wg]
//   [131072, 229376)   QKV: 128 rows x 768 cols = [Wq | Wk | Wv]
//   [229376, 245760)   CONV: 128 x 128
//   [245760, 253952)   FC: 128 x 64 (+pad)
#define WOFF_FC2 0
#define WOFF_QKV 131072
#define WOFF_CONV 229376
#define WOFF_FC 245760
#define WTOTAL 253952
__device__ __half g_wbuf[WTOTAL + 128];
// CSR machinery
__device__ int g_cnt[NN];
__device__ int g_rowptr[NN + 1];
__device__ int g_cursor[NN];
__device__ int g_csr[EE];
__device__ float g_f[NN];
__device__ int g_bsum[128];

// ---------------- utility ----------------
__global__ void zeros_all(float* red, float* ksum, float* kvs, int* cnt) {
    int i = blockIdx.x * blockDim.x + threadIdx.x;
    int stride = gridDim.x * blockDim.x;
    for (int j = i; j < 2 * HH * HH; j += stride) kvs[j] = 0.0f;
    for (int j = i; j < NN; j += stride) cnt[j] = 0;
    if (i < HH2) ksum[i] = 0.0f;
    if (i < 2) red[i] = 0.0f;
}

__device__ __forceinline__ float warpAllSum(float v) {
    unsigned m = 0xffffffffu;
    v += __shfl_xor_sync(m, v, 16);
    v += __shfl_xor_sync(m, v, 8);
    v += __shfl_xor_sync(m, v, 4);
    v += __shfl_xor_sync(m, v, 2);
    v += __shfl_xor_sync(m, v, 1);
    return v;
}

__device__ __forceinline__ float4 h4f(const __half* p) {
    uint2 u = *(const uint2*)p;
    __half2 h0 = *(__half2*)&u.x, h1 = *(__half2*)&u.y;
    float2 a = __half22float2(h0), b = __half22float2(h1);
    return make_float4(a.x, a.y, b.x, b.y);
}
__device__ __forceinline__ void f4h(__half* p, float4 v) {
    __half2 a = __floats2half2_rn(v.x, v.y), b = __floats2half2_rn(v.z, v.w);
    uint2 u;
    u.x = *(unsigned*)&a;
    u.y = *(unsigned*)&b;
    *(uint2*)p = u;
}
__device__ __forceinline__ void red_add_v4(float* p, float4 v) {
    asm volatile("red.global.add.v4.f32 [%0], {%1,%2,%3,%4};"
                 :: "l"(p), "f"(v.x), "f"(v.y), "f"(v.z), "f"(v.w) : "memory");
}
__device__ __forceinline__ void cp16h(__half* smem, const __half* gmem, bool pred) {
    unsigned saddr = (unsigned)__cvta_generic_to_shared(smem);
    int sz = pred ? 16 : 0;
    asm volatile("cp.async.cg.shared.global [%0], [%1], 16, %2;"
                 :: "r"(saddr), "l"(gmem), "r"(sz));
}

// x -> half
__global__ void x2h_kernel(const float* __restrict__ x, __half* __restrict__ xh) {
    size_t total4 = (size_t)NN * FF / 4;
    size_t i = (size_t)blockIdx.x * blockDim.x + threadIdx.x;
    size_t stride = (size_t)gridDim.x * blockDim.x;
    for (; i < total4; i += stride) {
        float4 v = ((const float4*)x)[i];
        f4h(xh + i * 4, v);
    }
}

// weights -> packed half layouts
__global__ void round_weights_kernel(const float* __restrict__ wt, const float* __restrict__ wg,
                                     const float* __restrict__ wq, const float* __restrict__ wk,
                                     const float* __restrict__ wv, const float* __restrict__ wc,
                                     const float* __restrict__ wf, __half* __restrict__ dst) {
    int i = blockIdx.x * blockDim.x + threadIdx.x;
    int stride = gridDim.x * blockDim.x;
    for (int j = i; j < WTOTAL + 128; j += stride) {
        float v;
        if (j < WOFF_QKV) {
            int r = j >> 8, c = j & 255;
            v = (c < 128) ? wt[r * 128 + c] : wg[r * 128 + (c - 128)];
        } else if (j < WOFF_CONV) {
            int j2 = j - WOFF_QKV;
            int r = j2 / 768, c = j2 % 768;
            int sel = c >> 8, cc = c & 255;
            v = (sel == 0) ? wq[r * 256 + cc] : (sel == 1) ? wk[r * 256 + cc] : wv[r * 256 + cc];
        } else if (j < WOFF_FC) {
            v = wc[j - WOFF_CONV];
        } else if (j < WTOTAL) {
            v = wf[j - WOFF_FC];
        } else v = 0.0f;
        dst[j] = __float2half_rn(v);
    }
}

// build block-diag half kvs2 from float kvs
__global__ void kvs2h_kernel(const float* __restrict__ kvs, __half* __restrict__ kvs2h) {
    int i = blockIdx.x * blockDim.x + threadIdx.x;
    int stride = gridDim.x * blockDim.x;
    for (int j = i; j < HH2 * HH2; j += stride) {
        int r = j >> 8, c = j & 255;
        int h = r >> 7;
        float v = ((c >> 7) == h) ? kvs[h * HH * HH + (r & 127) * HH + (c & 127)] : 0.0f;
        kvs2h[j] = __float2half_rn(v);
    }
}

// ---------------- fragment typedefs ----------------
typedef wmma::fragment<wmma::accumulator, 16, 16, 16, float> FragAcc;
typedef wmma::fragment<wmma::matrix_a, 16, 16, 16, __half, wmma::row_major> HFragA;
typedef wmma::fragment<wmma::matrix_a, 16, 16, 16, __half, wmma::col_major> HFragAT;
typedef wmma::fragment<wmma::matrix_b, 16, 16, 16, __half, wmma::row_major> HFragB;

#define BM 64
#define HA_LD 40
#define HA_STAGE (BM * HA_LD)   // 2560 halfs
#define NSTG 4

// ============ FP16 tensor GEMM core: BM=64, BN templated (64/128/256), BK=32, 4-stage ============
template <int BNT>
__device__ __forceinline__ void gemm_core_h(
    const __half* __restrict__ A, int lda, int M, int bm,
    const __half* __restrict__ B, int ldb, int bn,
    int K, float* smf) {
    __half* sm = (__half*)smf;
    constexpr int BS_LD = BNT + 8;
    constexpr int B_STAGE = 32 * BS_LD;
    constexpr int STG = HA_STAGE + B_STAGE;
    constexpr int WCW = (BNT == 128) ? 32 : ((BNT == 64) ? 16 : 64);
    constexpr int NFR = WCW / 16;

    const int tid = threadIdx.x;
    const int wid = tid >> 5;
    const int wr = wid >> 2;  // 0..1
    const int wc = wid & 3;   // 0..3

    FragAcc acc[2][NFR];
#pragma unroll
    for (int i = 0; i < 2; i++)
#pragma unroll
        for (int j = 0; j < NFR; j++) wmma::fill_fragment(acc[i][j], 0.0f);

    const int T = K >> 5;

    auto load_stage = [&](int t, int s) {
        const int k0 = t << 5;
        __half* sA = sm + s * STG;
        __half* sB = sm + s * STG + HA_STAGE;
        {
            int r = tid >> 2, c8 = (tid & 3) * 8;
            bool ok = (bm + r) < M;
            cp16h(sA + r * HA_LD + c8, A + (size_t)(ok ? bm + r : 0) * lda + k0 + c8, ok);
        }
        // B: 32 rows x BNT cols; 16B per thread-iteration
        constexpr int CPR = BNT / 8;           // float4-of-half groups per row
        constexpr int BITER = (32 * CPR + 255) / 256;
#pragma unroll
        for (int j = 0; j < BITER; j++) {
            int idx = tid + j * 256;
            if (32 * CPR > 256 || idx < 32 * CPR) {
                int r = idx / CPR, c8 = (idx % CPR) * 8;
                cp16h(sB + r * BS_LD + c8, B + (size_t)(k0 + r) * ldb + bn + c8, true);
            }
        }
        asm volatile("cp.async.commit_group;");
    };

#pragma unroll
    for (int t = 0; t < NSTG - 1; t++) {
        if (t < T) load_stage(t, t);
        else asm volatile("cp.async.commit_group;");
    }

    for (int t = 0; t < T; t++) {
        const int s = t & (NSTG - 1);
        asm volatile("cp.async.wait_group %0;" :: "n"(NSTG - 2));
        __syncthreads();
        int tn = t + NSTG - 1;
        if (tn < T) load_stage(tn, tn & (NSTG - 1));
        else asm volatile("cp.async.commit_group;");

        const __half* sA = sm + s * STG;
        const __half* sB = sm + s * STG + HA_STAGE;
#pragma unroll
        for (int ks = 0; ks < 2; ks++) {
            HFragA af[2];
#pragma unroll
            for (int mi = 0; mi < 2; mi++)
                wmma::load_matrix_sync(af[mi], sA + (wr * 32 + mi * 16) * HA_LD + ks * 16, HA_LD);
#pragma unroll
            for (int ni = 0; ni < NFR; ni++) {
                HFragB bf;
                wmma::load_matrix_sync(bf, sB + (ks * 16) * BS_LD + wc * WCW + ni * 16, BS_LD);
                wmma::mma_sync(acc[0][ni], af[0], bf, acc[0][ni]);
                wmma::mma_sync(acc[1][ni], af[1], bf, acc[1][ni]);
            }
        }
    }
    __syncthreads();

#pragma unroll
    for (int mi = 0; mi < 2; mi++)
#pragma unroll
        for (int ni = 0; ni < NFR; ni++)
            wmma::store_matrix_sync(smf + (wr * 32 + mi * 16) * BNT + wc * WCW + ni * 16,
                                    acc[mi][ni], BNT, wmma::mem_row_major);
    __syncthreads();
}

#define SM64 38912    // 4 stages * 4864 halfs * 2B (> 64*64*4 staging)
#define SM128 55296   // 4 stages * 6912 halfs * 2B
#define SM256 88064   // 4 stages * 11008 halfs * 2B (> 64*256*4 staging)

// ---- combined FC GEMM: C[:,0:128]=x@Wt -> LN -> ht ; C[:,128:256]=x@Wg -> BN -> hg
__global__ void __launch_bounds__(256, 2) gemm_fc_comb(
    const __half* __restrict__ xh, const __half* __restrict__ wbuf,
    const float* __restrict__ bt, const float* __restrict__ ln_g, const float* __restrict__ ln_b,
    const float* __restrict__ bg, const float* __restrict__ bn_g, const float* __restrict__ bn_b,
    __half* __restrict__ ht, __half* __restrict__ hg) {
    extern __shared__ float sm[];
    const int bm = blockIdx.x * BM;
    gemm_core_h<256>(xh, FF, NN, bm, wbuf + WOFF_FC2, HH2, 0, FF, sm);

    const int tid = threadIdx.x;
    const int wid = tid >> 5;
    const int lane = tid & 31;

    // LN part (cols 0..127)
    {
        float4 bb = *(const float4*)(bt + lane * 4);
        float4 gg = *(const float4*)(ln_g + lane * 4);
        float4 be = *(const float4*)(ln_b + lane * 4);
#pragma unroll
        for (int i = 0; i < 8; i++) {
            int r = wid * 8 + i;
            int m = bm + r;
            float4 v = *(float4*)(sm + r * 256 + lane * 4);
            v.x += bb.x; v.y += bb.y; v.z += bb.z; v.w += bb.w;
            float mu = warpAllSum(v.x + v.y + v.z + v.w) * (1.0f / 128.0f);
            float4 d = make_float4(v.x - mu, v.y - mu, v.z - mu, v.w - mu);
            float var = warpAllSum(d.x * d.x + d.y * d.y + d.z * d.z + d.w * d.w) * (1.0f / 128.0f);
            float rs = rsqrtf(var + LN_EPS);
            float4 o;
            o.x = fmaxf(d.x * rs * gg.x + be.x, 0.f);
            o.y = fmaxf(d.y * rs * gg.y + be.y, 0.f);
            o.z = fmaxf(d.z * rs * gg.z + be.z, 0.f);
            o.w = fmaxf(d.w * rs * gg.w + be.w, 0.f);
            if (m < NN) f4h(ht + (size_t)m * HH + lane * 4, o);
        }
    }
    // BN part (cols 128..255)
    {
        int c4 = lane * 4;
        int r0 = wid;
        const float sbn = rsqrtf(1.0f + LN_EPS);
        float4 bb = *(const float4*)(bg + c4);
        float4 gg = *(const float4*)(bn_g + c4);
        float4 be = *(const float4*)(bn_b + c4);
        gg.x *= sbn; gg.y *= sbn; gg.z *= sbn; gg.w *= sbn;
#pragma unroll
        for (int j = 0; j < 8; j++) {
            int r = r0 + j * 8;
            int m = bm + r;
            if (m < NN) {
                float4 v = *(float4*)(sm + r * 256 + 128 + c4);
                float4 o;
                o.x = fmaxf((v.x + bb.x) * gg.x + be.x, 0.f);
                o.y = fmaxf((v.y + bb.y) * gg.y + be.y, 0.f);
                o.z = fmaxf((v.z + bb.z) * gg.z + be.z, 0.f);
                o.w = fmaxf((v.w + bb.w) * gg.w + be.w, 0.f);
                f4h(hg + (size_t)m * HH + c4, o);
            }
        }
    }
}

// ---- QKV: grid.x = 3 (sel -> q/k/v, full 256-wide result) + norm/ksum reductions ----
__global__ void __launch_bounds__(256, 2) gemm_qkv(
    const __half* __restrict__ ht, const __half* __restrict__ wbuf,
    const float* __restrict__ bq, const float* __restrict__ bk, const float* __restrict__ bv,
    __half* __restrict__ q, __half* __restrict__ k, __half* __restrict__ v,
    float* __restrict__ red, float* __restrict__ ksum) {
    extern __shared__ float sm[];
    __shared__ float rsh[1];
    __shared__ float ks_s[HH2];
    const int sel = blockIdx.x;
    const int bm = blockIdx.y * BM;
    const float* bias = (sel == 0 ? bq : (sel == 1 ? bk : bv));
    __half* C = (sel == 0 ? q : (sel == 1 ? k : v));
    gemm_core_h<256>(ht, HH, NN, bm, wbuf + WOFF_QKV, 768, sel * 256, HH, sm);

    const int tid = threadIdx.x;
    int c4 = (tid & 63) * 4;        // 0..252
    int r0 = tid >> 6;              // 0..3
    float4 bb = *(const float4*)(bias + c4);

    if (sel == 1) ks_s[tid] = 0.0f;
    if (tid == 0) rsh[0] = 0.0f;
    __syncthreads();

    float sq = 0.0f;
    float4 cs = make_float4(0.f, 0.f, 0.f, 0.f);
#pragma unroll
    for (int j = 0; j < 16; j++) {
        int r = r0 + j * 4;
        int m = bm + r;
        if (m < NN) {
            float4 o = *(float4*)(sm + r * 256 + c4);
            o.x += bb.x; o.y += bb.y; o.z += bb.z; o.w += bb.w;
            if (sel < 2) sq += o.x * o.x + o.y * o.y + o.z * o.z + o.w * o.w;
            if (sel == 1) { cs.x += o.x; cs.y += o.y; cs.z += o.z; cs.w += o.w; }
            f4h(C + (size_t)m * HH2 + c4, o);
        }
    }

    if (sel < 2) {
        float ws = warpAllSum(sq);
        if ((tid & 31) == 0) atomicAdd(&rsh[0], ws);
        __syncthreads();
        if (tid == 0) atomicAdd(&red[sel], rsh[0]);
    }
    if (sel == 1) {
        atomicAdd(&ks_s[c4 + 0], cs.x);
        atomicAdd(&ks_s[c4 + 1], cs.y);
        atomicAdd(&ks_s[c4 + 2], cs.z);
        atomicAdd(&ks_s[c4 + 3], cs.w);
        __syncthreads();
        atomicAdd(&ksum[tid], ks_s[tid]);
    }
}

// ---- num over block-diag kvs2h + fused finalize -> x1 (half) ----
__global__ void __launch_bounds__(256, 2) gemm_num_fin(
    const __half* __restrict__ q, const __half* __restrict__ kvs2h,
    const __half* __restrict__ v, const __half* __restrict__ ht,
    const float* __restrict__ ksum, const float* __restrict__ red,
    const float* __restrict__ ln_g, const float* __restrict__ ln_b,
    __half* __restrict__ x1) {
    extern __shared__ float sm[];
    const int bm = blockIdx.x * BM;
    gemm_core_h<256>(q, HH2, NN, bm, kvs2h, HH2, 0, HH2, sm);

    const int tid = threadIdx.x;
    const int wid = tid >> 5;
    const int lane = tid & 31;
    const float inv = rsqrtf(red[0]) * rsqrtf(red[1]);

    float4 ka = *(const float4*)(ksum + lane * 8);
    float4 kb = *(const float4*)(ksum + lane * 8 + 4);
    float4 gg = *(const float4*)(ln_g + lane * 4);
    float4 be = *(const float4*)(ln_b + lane * 4);

#pragma unroll
    for (int i = 0; i < 8; i++) {
        int r = wid * 8 + i;
        int m = bm + r;
        if (m >= NN) continue;  // uniform per warp
        const __half* qrow = q + (size_t)m * HH2 + lane * 8;
        float4 qa = h4f(qrow);
        float4 qb = h4f(qrow + 4);
        float part = qa.x * ka.x + qa.y * ka.y + qa.z * ka.z + qa.w * ka.w
                   + qb.x * kb.x + qb.y * kb.y + qb.z * kb.z + qb.w * kb.w;
        float s0 = warpAllSum(lane < 16 ? part : 0.0f);
        float s1 = warpAllSum(lane >= 16 ? part : 0.0f);
        float nrm0 = inv * s0 + NFf;
        float nrm1 = inv * s1 + NFf;

        float4 n0 = *(float4*)(sm + r * 256 + lane * 4);
        float4 n1 = *(float4*)(sm + r * 256 + 128 + lane * 4);
        float4 v0 = h4f(v + (size_t)m * HH2 + lane * 4);
        float4 v1 = h4f(v + (size_t)m * HH2 + 128 + lane * 4);
        float4 hv = h4f(ht + (size_t)m * HH + lane * 4);

        float4 xv;
        xv.x = 0.5f * (0.5f * ((inv * n0.x + NFf * v0.x) / nrm0 + (inv * n1.x + NFf * v1.x) / nrm1) + hv.x);
        xv.y = 0.5f * (0.5f * ((inv * n0.y + NFf * v0.y) / nrm0 + (inv * n1.y + NFf * v1.y) / nrm1) + hv.y);
        xv.z = 0.5f * (0.5f * ((inv * n0.z + NFf * v0.z) / nrm0 + (inv * n1.z + NFf * v1.z) / nrm1) + hv.z);
        xv.w = 0.5f * (0.5f * ((inv * n0.w + NFf * v0.w) / nrm0 + (inv * n1.w + NFf * v1.w) / nrm1) + hv.w);

        float mu = warpAllSum(xv.x + xv.y + xv.z + xv.w) * (1.0f / 128.0f);
        float4 d = make_float4(xv.x - mu, xv.y - mu, xv.z - mu, xv.w - mu);
        float var = warpAllSum(d.x * d.x + d.y * d.y + d.z * d.z + d.w * d.w) * (1.0f / 128.0f);
        float rs = rsqrtf(var + LN_EPS);
        float4 o;
        o.x = fmaxf(d.x * rs * gg.x + be.x, 0.f);
        o.y = fmaxf(d.y * rs * gg.y + be.y, 0.f);
        o.z = fmaxf(d.z * rs * gg.z + be.z, 0.f);
        o.w = fmaxf(d.w * rs * gg.w + be.w, 0.f);
        f4h(x1 + (size_t)m * HH + lane * 4, o);
    }
}

// ---- conv GEMM + BN/relu/residual/mix -> y (half) ----
__global__ void __launch_bounds__(256, 3) gemm_conv_cmb(
    const __half* __restrict__ agg, const __half* __restrict__ wbuf,
    const float* __restrict__ bias, const float* __restrict__ bn_g, const float* __restrict__ bn_b,
    const __half* __restrict__ hg, const __half* __restrict__ x1,
    __half* __restrict__ y) {
    extern __shared__ float sm[];
    const int bm = blockIdx.x * BM;
    gemm_core_h<128>(agg, HH, NN, bm, wbuf + WOFF_CONV, HH, 0, HH, sm);

    const int tid = threadIdx.x;
    int c4 = (tid & 31) * 4;
    int r0 = tid >> 5;
    const float sbn = rsqrtf(1.0f + LN_EPS);
    float4 bb = *(const float4*)(bias + c4);
    float4 gg = *(const float4*)(bn_g + c4);
    float4 be = *(const float4*)(bn_b + c4);
    gg.x *= sbn; gg.y *= sbn; gg.z *= sbn; gg.w *= sbn;
#pragma unroll
    for (int j = 0; j < 8; j++) {
        int r = r0 + j * 8;
        int m = bm + r;
        if (m < NN) {
            float4 v = *(float4*)(sm + r * 128 + c4);
            v.x = fmaxf((v.x + bb.x) * gg.x + be.x, 0.f);
            v.y = fmaxf((v.y + bb.y) * gg.y + be.y, 0.f);
            v.z = fmaxf((v.z + bb.z) * gg.z + be.z, 0.f);
            v.w = fmaxf((v.w + bb.w) * gg.w + be.w, 0.f);
            float4 h = h4f(hg + (size_t)m * HH + c4);
            float4 xv = h4f(x1 + (size_t)m * HH + c4);
            float4 o;
            o.x = GW * (v.x + h.x) + (1.0f - GW) * xv.x;
            o.y = GW * (v.y + h.y) + (1.0f - GW) * xv.y;
            o.z = GW * (v.z + h.z) + (1.0f - GW) * xv.z;
            o.w = GW * (v.w + h.w) + (1.0f - GW) * xv.w;
            f4h(y + (size_t)m * HH + c4, o);
        }
    }
}

// ---- final head GEMM (true BN=64): out = y @ fc_w + fc_b (fp32 out) ----
__global__ void __launch_bounds__(256, 3) gemm_out(
    const __half* __restrict__ y, const __half* __restrict__ wbuf,
    const float* __restrict__ bias, float* __restrict__ out) {
    extern __shared__ float sm[];
    const int bm = blockIdx.x * BM;
    gemm_core_h<64>(y, HH, NN, bm, wbuf + WOFF_FC, CC, 0, HH, sm);

    const int tid = threadIdx.x;
    int c4 = (tid & 15) * 4;   // 0..60
    int r0 = tid >> 4;         // 0..15
    float4 bb = *(const float4*)(bias + c4);
#pragma unroll
    for (int j = 0; j < 4; j++) {
        int r = r0 + j * 16;
        int m = bm + r;
        if (m < NN) {
            float4 o = *(float4*)(sm + r * 64 + c4);
            o.x += bb.x; o.y += bb.y; o.z += bb.z; o.w += bb.w;
            *(float4*)(out + (size_t)m * CC + c4) = o;
        }
    }
}

// ============ FP16 split-K kvs -> float kvs (atomics), 3-stage pipeline ============
#define KVS_SMEM 65536
#define KS_LD 136
#define KVS_NSTG 3
#define KV_STG (2 * 32 * KS_LD)   // halfs per stage (K tile + V tile)

__global__ void __launch_bounds__(256) kvs_h_kernel(
    const __half* __restrict__ Km, const __half* __restrict__ Vm,
    float* __restrict__ kvs, int KC) {
    extern __shared__ float smf[];
    __half* base = (__half*)smf;

    const int tid = threadIdx.x;
    const int wid = tid >> 5;
    const int wr = wid >> 1;  // 0..3
    const int wc = wid & 1;   // 0..1
    const int head = blockIdx.y;
    const __half* Kp = Km + head * HH;
    const __half* Vp = Vm + head * HH;
    float* Cp = kvs + head * HH * HH;
    const int kb = blockIdx.x * KC;
    const int ke = min(kb + KC, NN);

    FragAcc acc[2][4];
#pragma unroll
    for (int i = 0; i < 2; i++)
#pragma unroll
        for (int j = 0; j < 4; j++) wmma::fill_fragment(acc[i][j], 0.0f);

    auto loadKV = [&](int t, int s) {
        __half* Ks = base + s * KV_STG;
        __half* Vs = Ks + 32 * KS_LD;
#pragma unroll
        for (int j = 0; j < 2; j++) {
            int idx = tid + j * 256;
            int r = idx >> 4, c8 = (idx & 15) * 8;
            int kr = t + r;
            bool ok = kr < ke;
            cp16h(Ks + r * KS_LD + c8, Kp + (size_t)(ok ? kr : 0) * HH2 + c8, ok);
            cp16h(Vs + r * KS_LD + c8, Vp + (size_t)(ok ? kr : 0) * HH2 + c8, ok);
        }
        asm volatile("cp.async.commit_group;");
    };

    // prologue
#pragma unroll
    for (int i = 0; i < KVS_NSTG - 1; i++) {
        if (kb + i * 32 < ke) loadKV(kb + i * 32, i);
        else asm volatile("cp.async.commit_group;");
    }

    int s = 0;
    for (int t = kb; t < ke; t += 32) {
        asm volatile("cp.async.wait_group %0;" :: "n"(KVS_NSTG - 2));
        __syncthreads();
        int tn = t + (KVS_NSTG - 1) * 32;
        int sn = s + KVS_NSTG - 1;
        if (sn >= KVS_NSTG) sn -= KVS_NSTG;
        if (tn < ke) loadKV(tn, sn);
        else asm volatile("cp.async.commit_group;");

        const __half* Ks = base + s * KV_STG;
        const __half* Vs = Ks + 32 * KS_LD;
#pragma unroll
        for (int ks = 0; ks < 2; ks++) {
            HFragAT af[2];
            wmma::load_matrix_sync(af[0], Ks + (ks * 16) * KS_LD + wr * 32, KS_LD);
            wmma::load_matrix_sync(af[1], Ks + (ks * 16) * KS_LD + wr * 32 + 16, KS_LD);
#pragma unroll
            for (int ni = 0; ni < 4; ni++) {
                HFragB bf;
                wmma::load_matrix_sync(bf, Vs + (ks * 16) * KS_LD + wc * 64 + ni * 16, KS_LD);
                wmma::mma_sync(acc[0][ni], af[0], bf, acc[0][ni]);
                wmma::mma_sync(acc[1][ni], af[1], bf, acc[1][ni]);
            }
        }
        if (++s == KVS_NSTG) s = 0;
    }
    __syncthreads();

    float* stg = smf;
#pragma unroll
    for (int mi = 0; mi < 2; mi++)
#pragma unroll
        for (int ni = 0; ni < 4; ni++)
            wmma::store_matrix_sync(stg + (wr * 32 + mi * 16) * 128 + wc * 64 + ni * 16,
                                    acc[mi][ni], 128, wmma::mem_row_major);
    __syncthreads();

    int oc = (tid & 31) * 4;
    int orr = tid >> 5;
#pragma unroll
    for (int j = 0; j < 16; j++) {
        int r = orr + j * 8;
        float4 v = *(float4*)(stg + r * 128 + oc);
        red_add_v4(Cp + r * 128 + oc, v);
    }
}

// ---------------- CSR build + gather ----------------
__global__ void deg_int_kernel(const int* __restrict__ ei, int* __restrict__ cnt) {
    int i = blockIdx.x * blockDim.x + threadIdx.x;
    int stride = gridDim.x * blockDim.x;
    for (int e = i; e < EE; e += stride) atomicAdd(&cnt[ei[EE + e]], 1);
}

__global__ void f_kernel(const int* __restrict__ cnt, float* __restrict__ f) {
    int i = blockIdx.x * blockDim.x + threadIdx.x;
    int stride = gridDim.x * blockDim.x;
    for (int n = i; n < NN; n += stride)
        f[n] = (cnt[n] > 0) ? rsqrtf((float)cnt[n]) : 0.0f;
}

#define SCAN_NB 98
__global__ void scan_partial(const int* __restrict__ cnt, int* __restrict__ bsum) {
    __shared__ int sh[32];
    int tid = threadIdx.x;
    int i = blockIdx.x * 1024 + tid;
    int v = (i < NN) ? cnt[i] : 0;
    unsigned m = 0xffffffffu;
    int s = v;
    s += __shfl_down_sync(m, s, 16);
    s += __shfl_down_sync(m, s, 8);
    s += __shfl_down_sync(m, s, 4);
    s += __shfl_down_sync(m, s, 2);
    s += __shfl_down_sync(m, s, 1);
    if ((tid & 31) == 0) sh[tid >> 5] = s;
    __syncthreads();
    if (tid < 32) {
        int t = sh[tid];
        t += __shfl_down_sync(m, t, 16);
        t += __shfl_down_sync(m, t, 8);
        t += __shfl_down_sync(m, t, 4);
        t += __shfl_down_sync(m, t, 2);
        t += __shfl_down_sync(m, t, 1);
        if (tid == 0) bsum[blockIdx.x] = t;
    }
}

__global__ void scan_bsum(int* __restrict__ bsum) {
    __shared__ int sh[128];
    int tid = threadIdx.x;
    int v = (tid < SCAN_NB) ? bsum[tid] : 0;
    sh[tid] = v;
    __syncthreads();
    for (int off = 1; off < 128; off <<= 1) {
        int t = (tid >= off) ? sh[tid - off] : 0;
        __syncthreads();
        sh[tid] += t;
        __syncthreads();
    }
    if (tid < SCAN_NB) bsum[tid] = sh[tid] - v;
}

__global__ void scan_final(const int* __restrict__ cnt, const int* __restrict__ bsum,
                           int* __restrict__ rowptr, int* __restrict__ cursor) {
    __shared__ int sh[1024];
    int tid = threadIdx.x;
    int i = blockIdx.x * 1024 + tid;
    int v = (i < NN) ? cnt[i] : 0;
    sh[tid] = v;
    __syncthreads();
    for (int off = 1; off < 1024; off <<= 1) {
        int t = (tid >= off) ? sh[tid - off] : 0;
        __syncthreads();
        sh[tid] += t;
        __syncthreads();
    }
    int ex = sh[tid] - v + bsum[blockIdx.x];
    if (i < NN) {
        rowptr[i] = ex;
        cursor[i] = ex;
    }
    if (i == NN - 1) rowptr[NN] = EE;
}

__global__ void fill_csr(const int* __restrict__ ei, int* __restrict__ cursor,
                         int* __restrict__ csr) {
    int i = blockIdx.x * blockDim.x + threadIdx.x;
    int stride = gridDim.x * blockDim.x;
    for (int e = i; e < EE; e += stride) {
        int c = ei[EE + e];
        int pos = atomicAdd(&cursor[c], 1);
        csr[pos] = ei[e];
    }
}

// one warp per node; lane owns 4 channels; unroll-4 for MLP
__global__ void gather_kernel(const int* __restrict__ rowptr, const int* __restrict__ csr,
                              const float* __restrict__ f, const __half* __restrict__ hg,
                              __half* __restrict__ agg) {
    int lane = threadIdx.x & 31;
    int w = (blockIdx.x * blockDim.x + threadIdx.x) >> 5;
    if (w >= NN) return;
    int n = w;
    int s = rowptr[n], e = rowptr[n + 1];
    float4 a0 = make_float4(0.f, 0.f, 0.f, 0.f);
    float4 a1 = make_float4(0.f, 0.f, 0.f, 0.f);
    int j = s;
    for (; j + 4 <= e; j += 4) {
        int r0 = csr[j], r1 = csr[j + 1], r2 = csr[j + 2], r3 = csr[j + 3];
        float f0 = f[r0], f1 = f[r1], f2 = f[r2], f3 = f[r3];
        float4 h0 = h4f(hg + (size_t)r0 * HH + lane * 4);
        float4 h1 = h4f(hg + (size_t)r1 * HH + lane * 4);
        float4 h2 = h4f(hg + (size_t)r2 * HH + lane * 4);
        float4 h3 = h4f(hg + (size_t)r3 * HH + lane * 4);
        a0.x += f0 * h0.x + f2 * h2.x; a0.y += f0 * h0.y + f2 * h2.y;
        a0.z += f0 * h0.z + f2 * h2.z; a0.w += f0 * h0.w + f2 * h2.w;
        a1.x += f1 * h1.x + f3 * h3.x; a1.y += f1 * h1.y + f3 * h3.y;
        a1.z += f1 * h1.z + f3 * h3.z; a1.w += f1 * h1.w + f3 * h3.w;
    }
    for (; j < e; j++) {
        int r = csr[j];
        float fr = f[r];
        float4 h = h4f(hg + (size_t)r * HH + lane * 4);
        a0.x += fr * h.x; a0.y += fr * h.y; a0.z += fr * h.z; a0.w += fr * h.w;
    }
    float fc = f[n];
    float4 acc = make_float4(fc * (a0.x + a1.x), fc * (a0.y + a1.y),
                             fc * (a0.z + a1.z), fc * (a0.w + a1.w));
    f4h(agg + (size_t)n * HH + lane * 4, acc);
}

// ---------------- host launcher ----------------
extern "C" void kernel_launch(void* const* d_in, const int* in_sizes, int n_in,
                              void* d_out, int out_size) {
    const float* x = (const float*)d_in[0];
    const int* ei = (const int*)d_in[1];
    const float* t_fc_w = (const float*)d_in[2];
    const float* t_fc_b = (const float*)d_in[3];
    const float* t_ln0_g = (const float*)d_in[4];
    const float* t_ln0_b = (const float*)d_in[5];
    const float* t_wq_w = (const float*)d_in[6];
    const float* t_wq_b = (const float*)d_in[7];
    const float* t_wk_w = (const float*)d_in[8];
    const float* t_wk_b = (const float*)d_in[9];
    const float* t_wv_w = (const float*)d_in[10];
    const float* t_wv_b = (const float*)d_in[11];
    const float* t_ln1_g = (const float*)d_in[12];
    const float* t_ln1_b = (const float*)d_in[13];
    const float* g_fc_w = (const float*)d_in[14];
    const float* g_fc_b = (const float*)d_in[15];
    const float* g_bn0_g = (const float*)d_in[16];
    const float* g_bn0_b = (const float*)d_in[17];
    const float* g_conv_w = (const float*)d_in[18];
    const float* g_conv_b = (const float*)d_in[19];
    const float* g_bn1_g = (const float*)d_in[20];
    const float* g_bn1_b = (const float*)d_in[21];
    const float* fc_w = (const float*)d_in[22];
    const float* fc_b = (const float*)d_in[23];
    float* out = (float*)d_out;

    cudaFuncSetAttribute(gemm_fc_comb, cudaFuncAttributeMaxDynamicSharedMemorySize, SM256);
    cudaFuncSetAttribute(gemm_qkv, cudaFuncAttributeMaxDynamicSharedMemorySize, SM256);
    cudaFuncSetAttribute(gemm_num_fin, cudaFuncAttributeMaxDynamicSharedMemorySize, SM256);
    cudaFuncSetAttribute(gemm_conv_cmb, cudaFuncAttributeMaxDynamicSharedMemorySize, SM128);
    cudaFuncSetAttribute(gemm_out, cudaFuncAttributeMaxDynamicSharedMemorySize, SM64);
    cudaFuncSetAttribute(kvs_h_kernel, cudaFuncAttributeMaxDynamicSharedMemorySize, KVS_SMEM);

    __half *p_xh, *p_ht, *p_hg, *p_q, *p_k, *p_v, *p_x1, *p_agg, *p_y, *p_kvs2h, *p_wbuf;
    float *p_kvs, *p_red, *p_ksum, *p_f;
    int *p_cnt, *p_rowptr, *p_cursor, *p_csr, *p_bsum;
    cudaGetSymbolAddress((void**)&p_xh, g_xh);
    cudaGetSymbolAddress((void**)&p_ht, g_ht);
    cudaGetSymbolAddress((void**)&p_hg, g_hg);
    cudaGetSymbolAddress((void**)&p_q, g_q);
    cudaGetSymbolAddress((void**)&p_k, g_k);
    cudaGetSymbolAddress((void**)&p_v, g_v);
    cudaGetSymbolAddress((void**)&p_x1, g_x1);
    cudaGetSymbolAddress((void**)&p_agg, g_agg);
    cudaGetSymbolAddress((void**)&p_y, g_y);
    cudaGetSymbolAddress((void**)&p_kvs2h, g_kvs2h);
    cudaGetSymbolAddress((void**)&p_wbuf, g_wbuf);
    cudaGetSymbolAddress((void**)&p_kvs, g_kvs);
    cudaGetSymbolAddress((void**)&p_red, g_red);
    cudaGetSymbolAddress((void**)&p_ksum, g_ksum);
    cudaGetSymbolAddress((void**)&p_f, g_f);
    cudaGetSymbolAddress((void**)&p_cnt, g_cnt);
    cudaGetSymbolAddress((void**)&p_rowptr, g_rowptr);
    cudaGetSymbolAddress((void**)&p_cursor, g_cursor);
    cudaGetSymbolAddress((void**)&p_csr, g_csr);
    cudaGetSymbolAddress((void**)&p_bsum, g_bsum);

    const int GY = (NN + BM - 1) / BM;  // 1563

    zeros_all<<<64, 256>>>(p_red, p_ksum, p_kvs, p_cnt);
    x2h_kernel<<<2048, 256>>>(x, p_xh);
    round_weights_kernel<<<248, 256>>>(t_fc_w, g_fc_w, t_wq_w, t_wk_w, t_wv_w,
                                       g_conv_w, fc_w, p_wbuf);

    // ---- combined FC (x read once; LN->ht, BN->hg) ----
    gemm_fc_comb<<<GY, 256, SM256>>>(
        p_xh, p_wbuf, t_fc_b, t_ln0_g, t_ln0_b, g_fc_b, g_bn0_g, g_bn0_b, p_ht, p_hg);

    // ---- QKV (BN=256, grid.x=3, + norms + ksum) ----
    gemm_qkv<<<dim3(3, GY), 256, SM256>>>(
        p_ht, p_wbuf, t_wq_b, t_wk_b, t_wv_b, p_q, p_k, p_v, p_red, p_ksum);

    // ---- kvs (fp16 MMA, 3-stage pipeline, fp32 atomic accumulate) ----
    {
        const int KC = 704;
        const int SPLITS = (NN + KC - 1) / KC;
        dim3 grid(SPLITS, 2);
        kvs_h_kernel<<<grid, 256, KVS_SMEM>>>(p_k, p_v, p_kvs, KC);
    }
    kvs2h_kernel<<<64, 256>>>(p_kvs, p_kvs2h);

    // ---- num GEMM + fused finalize -> x1 ----
    gemm_num_fin<<<GY, 256, SM256>>>(
        p_q, p_kvs2h, p_v, p_ht, p_ksum, p_red, t_ln1_g, t_ln1_b, p_x1);

    // ---- Graph branch (CSR + gather) ----
    deg_int_kernel<<<2048, 256>>>(ei, p_cnt);
    f_kernel<<<128, 256>>>(p_cnt, p_f);
    scan_partial<<<SCAN_NB, 1024>>>(p_cnt, p_bsum);
    scan_bsum<<<1, 128>>>(p_bsum);
    scan_final<<<SCAN_NB, 1024>>>(p_cnt, p_bsum, p_rowptr, p_cursor);
    fill_csr<<<2048, 256>>>(ei, p_cursor, p_csr);
    gather_kernel<<<(NN * 32 + 255) / 256, 256>>>(p_rowptr, p_csr, p_f, p_hg, p_agg);

    // ---- combine + head ----
    gemm_conv_cmb<<<GY, 256, SM128>>>(
        p_agg, p_wbuf, g_conv_b, g_bn1_g, g_bn1_b, p_hg, p_x1, p_y);

    gemm_out<<<GY, 256, SM64>>>(p_y, p_wbuf, fc_b, out);
}